// round 1
// baseline (speedup 1.0000x reference)
#include <cuda_runtime.h>
#include <cuda_bf16.h>

// GroupedEmbeddingBag: T tables, each [N, D] fp32; per table L indices pooled
// into B bags (sum pooling, include_last_offset). Output [B, T*D].
// Strategy: one warp per (t, b) bag. Lane l owns float4 slice [4l, 4l+4) of D=128.
// Every gathered row is one coalesced 512B warp transaction; accumulate in regs.

#define T_TABLES 8
#define N_ROWS   200000
#define D_DIM    128
#define B_BAGS   8192
#define L_IDX    163840

__global__ __launch_bounds__(256, 8)
void grouped_embedding_bag_kernel(const float*  __restrict__ weights,
                                  const int*    __restrict__ values,
                                  const int*    __restrict__ offsets,
                                  float*        __restrict__ out)
{
    const int warp_id = (blockIdx.x * blockDim.x + threadIdx.x) >> 5;
    const int lane    = threadIdx.x & 31;
    // warp_id in [0, T*B): t-major so offset reads stream per table
    const int t = warp_id >> 13;          // / B_BAGS (8192 = 2^13)
    const int b = warp_id & (B_BAGS - 1);

    const int* __restrict__ offs_t = offsets + t * (B_BAGS + 1) + b;
    const int start = __ldg(offs_t);
    const int end   = __ldg(offs_t + 1);

    const int* __restrict__ vals_t = values + (size_t)t * L_IDX;
    // Row stride in float4 units: D/4 = 32. Lane l reads float4 #l of each row.
    const float4* __restrict__ base =
        reinterpret_cast<const float4*>(weights + (size_t)t * N_ROWS * D_DIM) + lane;

    float4 acc = make_float4(0.f, 0.f, 0.f, 0.f);

    int i = start;
    // Unroll by 4: 4 independent 512B row gathers in flight per warp (MLP for DRAM).
    for (; i + 4 <= end; i += 4) {
        const int i0 = __ldg(vals_t + i);
        const int i1 = __ldg(vals_t + i + 1);
        const int i2 = __ldg(vals_t + i + 2);
        const int i3 = __ldg(vals_t + i + 3);
        const float4 v0 = __ldg(base + (size_t)i0 * 32);
        const float4 v1 = __ldg(base + (size_t)i1 * 32);
        const float4 v2 = __ldg(base + (size_t)i2 * 32);
        const float4 v3 = __ldg(base + (size_t)i3 * 32);
        // pairwise to shorten the dependent FADD chain
        acc.x += (v0.x + v1.x) + (v2.x + v3.x);
        acc.y += (v0.y + v1.y) + (v2.y + v3.y);
        acc.z += (v0.z + v1.z) + (v2.z + v3.z);
        acc.w += (v0.w + v1.w) + (v2.w + v3.w);
    }
    for (; i < end; ++i) {
        const int idx = __ldg(vals_t + i);
        const float4 v = __ldg(base + (size_t)idx * 32);
        acc.x += v.x; acc.y += v.y; acc.z += v.z; acc.w += v.w;
    }

    // out[b, t*D + 4*lane .. +3]  (coalesced 512B store per warp)
    float4* __restrict__ o =
        reinterpret_cast<float4*>(out + (size_t)b * (T_TABLES * D_DIM) + t * D_DIM) + lane;
    *o = acc;
}

extern "C" void kernel_launch(void* const* d_in, const int* in_sizes, int n_in,
                              void* d_out, int out_size)
{
    const float* weights = (const float*)d_in[0];  // [T, N, D] f32
    const int*   values  = (const int*)  d_in[1];  // [T, L]    i32
    const int*   offsets = (const int*)  d_in[2];  // [T, B+1]  i32
    float*       out     = (float*)d_out;          // [B, T*D]  f32

    // T*B warps total, 8 warps (256 threads) per block
    const int total_warps = T_TABLES * B_BAGS;      // 65536
    const int blocks = total_warps / 8;             // 8192
    grouped_embedding_bag_kernel<<<blocks, 256>>>(weights, values, offsets, out);
}

// round 3
// speedup vs baseline: 1.3337x; 1.3337x over previous
#include <cuda_runtime.h>
#include <cuda_bf16.h>

// GroupedEmbeddingBag: T tables [N, D] fp32; per table L indices pooled into B
// bags (sum, include_last_offset). Output [B, T*D].
//
// R2 strategy (retry after infra timeout): one 128-thread CTA per (t, b) bag.
// The 4 warps split the bag's indices interleaved (warp k takes i = start+k,
// start+k+4, ...), so per-scheduler work variance drops 4x vs warp-per-bag
// (bag sizes are ~exponential, mean 20, max ~180). Lane l owns float4 slice
// [4l,4l+4) of D=128 -> every row gather is one coalesced 512B warp
// transaction. Partials reduced via smem, one coalesced 512B store.
// Empty bags naturally store zeros.

#define T_TABLES 8
#define N_ROWS   200000
#define D_DIM    128
#define B_BAGS   8192
#define L_IDX    163840

__global__ __launch_bounds__(128, 16)
void grouped_embedding_bag_kernel(const float*  __restrict__ weights,
                                  const int*    __restrict__ values,
                                  const int*    __restrict__ offsets,
                                  float*        __restrict__ out)
{
    const int t = blockIdx.x >> 13;           // / B_BAGS
    const int b = blockIdx.x & (B_BAGS - 1);
    const int warp = threadIdx.x >> 5;        // 0..3
    const int lane = threadIdx.x & 31;

    const int* __restrict__ offs_t = offsets + t * (B_BAGS + 1) + b;
    const int start = __ldg(offs_t);
    const int end   = __ldg(offs_t + 1);

    const int* __restrict__ vals_t = values + (size_t)t * L_IDX;
    const float4* __restrict__ base =
        reinterpret_cast<const float4*>(weights + (size_t)t * N_ROWS * D_DIM) + lane;

    float4 acc = make_float4(0.f, 0.f, 0.f, 0.f);

    // Warp `warp` handles indices start+warp, start+warp+4, ... (stride 4).
    // Unroll by 4 (stride 16) to keep 4 independent 512B row loads in flight.
    int i = start + warp;
    for (; i + 12 < end; i += 16) {
        const int i0 = __ldg(vals_t + i);
        const int i1 = __ldg(vals_t + i + 4);
        const int i2 = __ldg(vals_t + i + 8);
        const int i3 = __ldg(vals_t + i + 12);
        const float4 v0 = __ldg(base + (size_t)i0 * 32);
        const float4 v1 = __ldg(base + (size_t)i1 * 32);
        const float4 v2 = __ldg(base + (size_t)i2 * 32);
        const float4 v3 = __ldg(base + (size_t)i3 * 32);
        acc.x += (v0.x + v1.x) + (v2.x + v3.x);
        acc.y += (v0.y + v1.y) + (v2.y + v3.y);
        acc.z += (v0.z + v1.z) + (v2.z + v3.z);
        acc.w += (v0.w + v1.w) + (v2.w + v3.w);
    }
    for (; i < end; i += 4) {
        const int idx = __ldg(vals_t + i);
        const float4 v = __ldg(base + (size_t)idx * 32);
        acc.x += v.x; acc.y += v.y; acc.z += v.z; acc.w += v.w;
    }

    // Reduce 4 warps' partials through smem.
    __shared__ float4 red[4][32];
    red[warp][lane] = acc;
    __syncthreads();

    if (warp == 0) {
        const float4 a1 = red[1][lane];
        const float4 a2 = red[2][lane];
        const float4 a3 = red[3][lane];
        acc.x += (a1.x + a2.x) + a3.x;
        acc.y += (a1.y + a2.y) + a3.y;
        acc.z += (a1.z + a2.z) + a3.z;
        acc.w += (a1.w + a2.w) + a3.w;
        float4* __restrict__ o =
            reinterpret_cast<float4*>(out + (size_t)b * (T_TABLES * D_DIM) + t * D_DIM) + lane;
        *o = acc;
    }
}

extern "C" void kernel_launch(void* const* d_in, const int* in_sizes, int n_in,
                              void* d_out, int out_size)
{
    const float* weights = (const float*)d_in[0];  // [T, N, D] f32
    const int*   values  = (const int*)  d_in[1];  // [T, L]    i32
    const int*   offsets = (const int*)  d_in[2];  // [T, B+1]  i32
    float*       out     = (float*)d_out;          // [B, T*D]  f32

    const int blocks = T_TABLES * B_BAGS;          // 65536 CTAs, one per bag
    grouped_embedding_bag_kernel<<<blocks, 128>>>(weights, values, offsets, out);
}